// round 1
// baseline (speedup 1.0000x reference)
#include <cuda_runtime.h>
#include <math.h>

#define BB 4
#define NN 4096
#define DD 128

// Scratch: E = exp(S) [B,N,N] fp32, and column sums l[b,k].
__device__ float g_E[(size_t)BB * NN * NN];
__device__ float g_l[BB * NN];

__global__ void zero_l_kernel() {
    int i = blockIdx.x * blockDim.x + threadIdx.x;
    if (i < BB * NN) g_l[i] = 0.0f;
}

// Kernel 1: E[b,q,k] = exp(q·k / sqrt(128)); atomically accumulate l[b,k] = sum_q E.
// 128x128 tile per block, 256 threads, 8x8 microtile, k-chunk (over D) = 8.
__global__ __launch_bounds__(256) void qk_exp_kernel(const float* __restrict__ Q,
                                                     const float* __restrict__ K) {
    const int b  = blockIdx.z;
    const int qb = blockIdx.y * 128;
    const int kb = blockIdx.x * 128;

    __shared__ float As[8][128];   // [d][q]
    __shared__ float Bs[8][128];   // [d][k]

    const float* Qb = Q + (size_t)b * NN * DD;
    const float* Kb = K + (size_t)b * NN * DD;

    const int tid = threadIdx.x;
    const int tr  = tid >> 4;        // 0..15  -> q micro-rows tr*8..tr*8+7
    const int tc  = tid & 15;        // 0..15  -> k micro-cols tc*8..tc*8+7
    const int lrow  = tid >> 1;      // 0..127
    const int lhalf = (tid & 1) * 4; // 0 or 4

    float acc[8][8];
#pragma unroll
    for (int i = 0; i < 8; i++)
#pragma unroll
        for (int j = 0; j < 8; j++) acc[i][j] = 0.0f;

    for (int d0 = 0; d0 < DD; d0 += 8) {
        float4 a4 = *(const float4*)(Qb + (size_t)(qb + lrow) * DD + d0 + lhalf);
        float4 b4 = *(const float4*)(Kb + (size_t)(kb + lrow) * DD + d0 + lhalf);
        __syncthreads();
        As[lhalf + 0][lrow] = a4.x; As[lhalf + 1][lrow] = a4.y;
        As[lhalf + 2][lrow] = a4.z; As[lhalf + 3][lrow] = a4.w;
        Bs[lhalf + 0][lrow] = b4.x; Bs[lhalf + 1][lrow] = b4.y;
        Bs[lhalf + 2][lrow] = b4.z; Bs[lhalf + 3][lrow] = b4.w;
        __syncthreads();
#pragma unroll
        for (int dd = 0; dd < 8; dd++) {
            float ra[8], rb[8];
            *(float4*)(ra)     = *(const float4*)&As[dd][tr * 8];
            *(float4*)(ra + 4) = *(const float4*)&As[dd][tr * 8 + 4];
            *(float4*)(rb)     = *(const float4*)&Bs[dd][tc * 8];
            *(float4*)(rb + 4) = *(const float4*)&Bs[dd][tc * 8 + 4];
#pragma unroll
            for (int i = 0; i < 8; i++)
#pragma unroll
                for (int j = 0; j < 8; j++) acc[i][j] += ra[i] * rb[j];
        }
    }

    const float SCALE = 0.08838834764831845f;  // 1/sqrt(128)
    float csum[8];
#pragma unroll
    for (int j = 0; j < 8; j++) csum[j] = 0.0f;

#pragma unroll
    for (int i = 0; i < 8; i++) {
        const size_t q = (size_t)(qb + tr * 8 + i);
        float e[8];
#pragma unroll
        for (int j = 0; j < 8; j++) {
            e[j] = __expf(acc[i][j] * SCALE);
            csum[j] += e[j];
        }
        float* dst = g_E + ((size_t)b * NN + q) * NN + kb + tc * 8;
        *(float4*)(dst)     = make_float4(e[0], e[1], e[2], e[3]);
        *(float4*)(dst + 4) = make_float4(e[4], e[5], e[6], e[7]);
    }
#pragma unroll
    for (int j = 0; j < 8; j++)
        atomicAdd(&g_l[b * NN + kb + tc * 8 + j], csum[j]);
}

// Kernel 2: O[b,q,d] = sum_k (E[b,q,k] / l[b,k]) * V[b,k,d].
// 128(q) x 128(d) tile per block, k-chunks of 8; 1/l folded into V tile load.
__global__ __launch_bounds__(256) void pv_kernel(const float* __restrict__ V,
                                                 float* __restrict__ O) {
    const int b  = blockIdx.y;
    const int qb = blockIdx.x * 128;

    __shared__ float Es[8][128];   // [k][q]
    __shared__ float Vs[8][128];   // [k][d]  (pre-scaled by 1/l[k])

    const float* Vb = V + (size_t)b * NN * DD;
    const float* Eb = g_E + (size_t)b * NN * NN;

    const int tid = threadIdx.x;
    const int tr  = tid >> 4;
    const int tc  = tid & 15;
    const int lrow  = tid >> 1;
    const int lhalf = (tid & 1) * 4;
    const int vrow  = tid >> 5;        // 0..7
    const int vcol  = (tid & 31) * 4;  // 0..124

    float acc[8][8];
#pragma unroll
    for (int i = 0; i < 8; i++)
#pragma unroll
        for (int j = 0; j < 8; j++) acc[i][j] = 0.0f;

    for (int k0 = 0; k0 < NN; k0 += 8) {
        float4 e4 = *(const float4*)(Eb + (size_t)(qb + lrow) * NN + k0 + lhalf);
        float4 v4 = *(const float4*)(Vb + (size_t)(k0 + vrow) * DD + vcol);
        const float linv = 1.0f / g_l[b * NN + k0 + vrow];
        v4.x *= linv; v4.y *= linv; v4.z *= linv; v4.w *= linv;
        __syncthreads();
        Es[lhalf + 0][lrow] = e4.x; Es[lhalf + 1][lrow] = e4.y;
        Es[lhalf + 2][lrow] = e4.z; Es[lhalf + 3][lrow] = e4.w;
        *(float4*)&Vs[vrow][vcol] = v4;
        __syncthreads();
#pragma unroll
        for (int dd = 0; dd < 8; dd++) {
            float ra[8], rb[8];
            *(float4*)(ra)     = *(const float4*)&Es[dd][tr * 8];
            *(float4*)(ra + 4) = *(const float4*)&Es[dd][tr * 8 + 4];
            *(float4*)(rb)     = *(const float4*)&Vs[dd][tc * 8];
            *(float4*)(rb + 4) = *(const float4*)&Vs[dd][tc * 8 + 4];
#pragma unroll
            for (int i = 0; i < 8; i++)
#pragma unroll
                for (int j = 0; j < 8; j++) acc[i][j] += ra[i] * rb[j];
        }
    }

#pragma unroll
    for (int i = 0; i < 8; i++) {
        float* dst = O + ((size_t)b * NN + (qb + tr * 8 + i)) * DD + tc * 8;
        *(float4*)(dst)     = make_float4(acc[i][0], acc[i][1], acc[i][2], acc[i][3]);
        *(float4*)(dst + 4) = make_float4(acc[i][4], acc[i][5], acc[i][6], acc[i][7]);
    }
}

extern "C" void kernel_launch(void* const* d_in, const int* in_sizes, int n_in,
                              void* d_out, int out_size) {
    const float* q = (const float*)d_in[0];
    const float* k = (const float*)d_in[1];
    const float* v = (const float*)d_in[2];
    float* out = (float*)d_out;

    zero_l_kernel<<<(BB * NN + 255) / 256, 256>>>();

    dim3 g1(NN / 128, NN / 128, BB);
    qk_exp_kernel<<<g1, 256>>>(q, k);

    dim3 g2(NN / 128, BB);
    pv_kernel<<<g2, 256>>>(v, out);
}

// round 4
// speedup vs baseline: 3.2393x; 3.2393x over previous
#include <cuda_runtime.h>
#include <math.h>
#include <stdint.h>

#define BB 4
#define NN 4096
#define DD 128

// ---------------- scratch (device globals; allocation-free) ----------------
__device__ float g_E[(size_t)BB * NN * NN];   // exp(S), tf32-rounded
__device__ float g_l[BB * NN];                // column sums over q
__device__ float g_Qt[(size_t)BB * NN * DD];  // RNA-tf32 rounded Q
__device__ float g_Kt[(size_t)BB * NN * DD];  // RNA-tf32 rounded K
__device__ float g_VT[(size_t)BB * DD * NN];  // V^T scaled by 1/l, tf32-rounded

// ---------------- helpers ----------------
__device__ __forceinline__ uint32_t smem_u32(const void* p) {
    uint32_t a;
    asm("{ .reg .u64 t; cvta.to.shared.u64 t, %1; cvt.u32.u64 %0, t; }" : "=r"(a) : "l"(p));
    return a;
}
__device__ __forceinline__ float to_tf32(float x) {
    uint32_t u;
    asm("cvt.rna.tf32.f32 %0, %1;" : "=r"(u) : "f"(x));
    return __uint_as_float(u);
}

#define CP_ASYNC16(s, g) asm volatile("cp.async.cg.shared.global [%0], [%1], 16;" :: "r"(s), "l"(g))
#define CP_COMMIT()      asm volatile("cp.async.commit_group;" ::: "memory")
#define CP_WAIT(n)       asm volatile("cp.async.wait_group %0;" :: "n"(n) : "memory")

// m16n8k8 tf32 MMA, fp32 accumulate (baseline PTX, sm_80+)
__device__ __forceinline__ void mma_tf32(float* c, const uint32_t* a, const uint32_t* b) {
    asm volatile(
        "mma.sync.aligned.m16n8k8.row.col.f32.tf32.tf32.f32 "
        "{%0,%1,%2,%3}, {%4,%5,%6,%7}, {%8,%9}, {%0,%1,%2,%3};"
        : "+f"(c[0]), "+f"(c[1]), "+f"(c[2]), "+f"(c[3])
        : "r"(a[0]), "r"(a[1]), "r"(a[2]), "r"(a[3]), "r"(b[0]), "r"(b[1]));
}

// SMEM tile: rows x 32 floats, row stride 36 floats (144B) -> conflict-free frags
__device__ __forceinline__ void load_tile128(uint32_t sdst, const float* g, size_t rstride, int tid) {
#pragma unroll
    for (int i = 0; i < 4; i++) {
        int idx = i * 256 + tid;
        int row = idx >> 3, c4 = idx & 7;
        CP_ASYNC16(sdst + row * 144 + c4 * 16, g + (size_t)row * rstride + c4 * 4);
    }
}
__device__ __forceinline__ void load_tile64(uint32_t sdst, const float* g, size_t rstride, int tid) {
#pragma unroll
    for (int i = 0; i < 2; i++) {
        int idx = i * 256 + tid;
        int row = idx >> 3, c4 = idx & 7;
        CP_ASYNC16(sdst + row * 144 + c4 * 16, g + (size_t)row * rstride + c4 * 4);
    }
}

// ---------------- small kernels ----------------
__global__ void zero_l_kernel() {
    int i = blockIdx.x * blockDim.x + threadIdx.x;
    if (i < BB * NN) g_l[i] = 0.0f;
}
__global__ void cvt_kernel(const float* __restrict__ Q, const float* __restrict__ K) {
    size_t n = (size_t)BB * NN * DD;
    size_t i = (size_t)blockIdx.x * blockDim.x + threadIdx.x;
    if (i < n) {
        g_Qt[i] = to_tf32(Q[i]);
        g_Kt[i] = to_tf32(K[i]);
    }
}
// VT[b][d][k] = rna(V[b][k][d] / l[b][k])
__global__ void vt_kernel(const float* __restrict__ V) {
    __shared__ float ts[32][33];
    int b = blockIdx.z, d0 = blockIdx.y * 32, k0 = blockIdx.x * 32;
    int tx = threadIdx.x, ty = threadIdx.y;
    const float* Vb = V + (size_t)b * NN * DD;
#pragma unroll
    for (int i = 0; i < 4; i++) {
        int r = ty + i * 8;
        ts[r][tx] = Vb[(size_t)(k0 + r) * DD + d0 + tx];
    }
    __syncthreads();
    float linv = 1.0f / g_l[b * NN + k0 + tx];
#pragma unroll
    for (int i = 0; i < 4; i++) {
        int d = ty + i * 8;
        g_VT[((size_t)b * DD + d0 + d) * NN + k0 + tx] = to_tf32(ts[tx][d] * linv);
    }
}

// ---------------- kernel 1: E = exp(QK^T/sqrt(D)), l = colsum(E) ----------------
// grid (32 kt, 32 qt, 4 b), 256 threads (8 warps, 2x4), tile 128x128, K=128 in 4 chunks.
#define TILEB (128 * 36 * 4)  // 18432
#define SM1 (4 * TILEB)       // A dbl + B dbl = 73728
__global__ __launch_bounds__(256, 2) void qk_exp_kernel() {
    const int b = blockIdx.z, qb = blockIdx.y * 128, kb = blockIdx.x * 128;
    const int tid = threadIdx.x, lane = tid & 31, wid = tid >> 5;
    const int wm = wid >> 2, wn = wid & 3;

    extern __shared__ __align__(16) char dyn[];
    uint32_t sbase = smem_u32(dyn);
    uint32_t sA[2] = { sbase, sbase + TILEB };
    uint32_t sB[2] = { sbase + 2 * TILEB, sbase + 3 * TILEB };
    const float* fA[2] = { (const float*)dyn, (const float*)(dyn + TILEB) };
    const float* fB[2] = { (const float*)(dyn + 2 * TILEB), (const float*)(dyn + 3 * TILEB) };

    const float* Qg = g_Qt + ((size_t)b * NN + qb) * DD;
    const float* Kg = g_Kt + ((size_t)b * NN + kb) * DD;

    float acc[4][4][4];
#pragma unroll
    for (int i = 0; i < 4; i++)
#pragma unroll
        for (int j = 0; j < 4; j++)
#pragma unroll
            for (int t = 0; t < 4; t++) acc[i][j][t] = 0.0f;

    load_tile128(sA[0], Qg, DD, tid);
    load_tile128(sB[0], Kg, DD, tid);
    CP_COMMIT();

#pragma unroll 1
    for (int c = 0; c < 4; c++) {
        if (c + 1 < 4) {
            load_tile128(sA[(c + 1) & 1], Qg + (c + 1) * 32, DD, tid);
            load_tile128(sB[(c + 1) & 1], Kg + (c + 1) * 32, DD, tid);
            CP_COMMIT();
            CP_WAIT(1);
        } else {
            CP_WAIT(0);
        }
        __syncthreads();
        const float* A = fA[c & 1];
        const float* B = fB[c & 1];
#pragma unroll
        for (int ks = 0; ks < 4; ks++) {
            const int k0 = ks * 8;
            uint32_t af[4][4], bf[4][2];
#pragma unroll
            for (int i = 0; i < 4; i++) {
                int r0 = wm * 64 + i * 16 + (lane >> 2);
                af[i][0] = __float_as_uint(A[r0 * 36 + k0 + (lane & 3)]);
                af[i][1] = __float_as_uint(A[(r0 + 8) * 36 + k0 + (lane & 3)]);
                af[i][2] = __float_as_uint(A[r0 * 36 + k0 + 4 + (lane & 3)]);
                af[i][3] = __float_as_uint(A[(r0 + 8) * 36 + k0 + 4 + (lane & 3)]);
            }
#pragma unroll
            for (int j = 0; j < 4; j++) {
                int n0 = wn * 32 + j * 8 + (lane >> 2);
                bf[j][0] = __float_as_uint(B[n0 * 36 + k0 + (lane & 3)]);
                bf[j][1] = __float_as_uint(B[n0 * 36 + k0 + 4 + (lane & 3)]);
            }
#pragma unroll
            for (int i = 0; i < 4; i++)
#pragma unroll
                for (int j = 0; j < 4; j++) mma_tf32(acc[i][j], af[i], bf[j]);
        }
        __syncthreads();
    }

    // epilogue: exp, tf32-round, store E, column sums
    const float SCALE = 0.08838834764831845f;
    float csum[4][2];
#pragma unroll
    for (int j = 0; j < 4; j++) { csum[j][0] = 0.0f; csum[j][1] = 0.0f; }

#pragma unroll
    for (int i = 0; i < 4; i++) {
        const int row0 = qb + wm * 64 + i * 16 + (lane >> 2);
#pragma unroll
        for (int j = 0; j < 4; j++) {
            float e0 = to_tf32(__expf(acc[i][j][0] * SCALE));
            float e1 = to_tf32(__expf(acc[i][j][1] * SCALE));
            float e2 = to_tf32(__expf(acc[i][j][2] * SCALE));
            float e3 = to_tf32(__expf(acc[i][j][3] * SCALE));
            const int col = kb + wn * 32 + j * 8 + (lane & 3) * 2;
            float2* p0 = (float2*)(g_E + ((size_t)b * NN + row0) * NN + col);
            float2* p1 = (float2*)(g_E + ((size_t)b * NN + row0 + 8) * NN + col);
            *p0 = make_float2(e0, e1);
            *p1 = make_float2(e2, e3);
            csum[j][0] += e0 + e2;
            csum[j][1] += e1 + e3;
        }
    }
#pragma unroll
    for (int j = 0; j < 4; j++) {
#pragma unroll
        for (int p = 0; p < 2; p++) {
            float v = csum[j][p];
            v += __shfl_xor_sync(0xffffffffu, v, 4);
            v += __shfl_xor_sync(0xffffffffu, v, 8);
            v += __shfl_xor_sync(0xffffffffu, v, 16);
            if (lane < 4)
                atomicAdd(&g_l[b * NN + kb + wn * 32 + j * 8 + lane * 2 + p], v);
        }
    }
}

// ---------------- kernel 2: O = E_norm @ V ----------------
// grid (64 qt, 4 b), 256 threads (2x4 warps), tile 64(q) x 128(d), K=4096 in 128 chunks.
#define TILEB64 (64 * 36 * 4)          // 9216
#define SM2 (2 * TILEB64 + 2 * TILEB)  // 55296
__global__ __launch_bounds__(256, 2) void pv_kernel(float* __restrict__ O) {
    const int b = blockIdx.y, qb = blockIdx.x * 64;
    const int tid = threadIdx.x, lane = tid & 31, wid = tid >> 5;
    const int wm = wid >> 2, wn = wid & 3;

    extern __shared__ __align__(16) char dyn[];
    uint32_t sbase = smem_u32(dyn);
    uint32_t sA[2] = { sbase, sbase + TILEB64 };
    uint32_t sB[2] = { sbase + 2 * TILEB64, sbase + 2 * TILEB64 + TILEB };
    const float* fA[2] = { (const float*)dyn, (const float*)(dyn + TILEB64) };
    const float* fB[2] = { (const float*)(dyn + 2 * TILEB64),
                           (const float*)(dyn + 2 * TILEB64 + TILEB) };

    const float* Eg = g_E + ((size_t)b * NN + qb) * NN;
    const float* Vg = g_VT + (size_t)b * DD * NN;

    float acc[2][4][4];
#pragma unroll
    for (int i = 0; i < 2; i++)
#pragma unroll
        for (int j = 0; j < 4; j++)
#pragma unroll
            for (int t = 0; t < 4; t++) acc[i][j][t] = 0.0f;

    load_tile64(sA[0], Eg, NN, tid);
    load_tile128(sB[0], Vg, NN, tid);
    CP_COMMIT();

#pragma unroll 1
    for (int c = 0; c < 128; c++) {
        if (c + 1 < 128) {
            load_tile64(sA[(c + 1) & 1], Eg + (size_t)(c + 1) * 32, NN, tid);
            load_tile128(sB[(c + 1) & 1], Vg + (size_t)(c + 1) * 32, NN, tid);
            CP_COMMIT();
            CP_WAIT(1);
        } else {
            CP_WAIT(0);
        }
        __syncthreads();
        const float* A = fA[c & 1];
        const float* B = fB[c & 1];
#pragma unroll
        for (int ks = 0; ks < 4; ks++) {
            const int k0 = ks * 8;
            uint32_t af[2][4], bf[4][2];
#pragma unroll
            for (int i = 0; i < 2; i++) {
                int r0 = wm * 32 + i * 16 + (lane >> 2);
                af[i][0] = __float_as_uint(A[r0 * 36 + k0 + (lane & 3)]);
                af[i][1] = __float_as_uint(A[(r0 + 8) * 36 + k0 + (lane & 3)]);
                af[i][2] = __float_as_uint(A[r0 * 36 + k0 + 4 + (lane & 3)]);
                af[i][3] = __float_as_uint(A[(r0 + 8) * 36 + k0 + 4 + (lane & 3)]);
            }
#pragma unroll
            for (int j = 0; j < 4; j++) {
                int n0 = wn * 32 + j * 8 + (lane >> 2);
                bf[j][0] = __float_as_uint(B[n0 * 36 + k0 + (lane & 3)]);
                bf[j][1] = __float_as_uint(B[n0 * 36 + k0 + 4 + (lane & 3)]);
            }
#pragma unroll
            for (int i = 0; i < 2; i++)
#pragma unroll
                for (int j = 0; j < 4; j++) mma_tf32(acc[i][j], af[i], bf[j]);
        }
        __syncthreads();
    }

#pragma unroll
    for (int i = 0; i < 2; i++) {
        const int row0 = qb + wm * 32 + i * 16 + (lane >> 2);
#pragma unroll
        for (int j = 0; j < 4; j++) {
            const int col = wn * 32 + j * 8 + (lane & 3) * 2;
            float2* p0 = (float2*)(O + ((size_t)b * NN + row0) * DD + col);
            float2* p1 = (float2*)(O + ((size_t)b * NN + row0 + 8) * DD + col);
            *p0 = make_float2(acc[i][j][0], acc[i][j][1]);
            *p1 = make_float2(acc[i][j][2], acc[i][j][3]);
        }
    }
}

// ---------------- launch ----------------
extern "C" void kernel_launch(void* const* d_in, const int* in_sizes, int n_in,
                              void* d_out, int out_size) {
    const float* q = (const float*)d_in[0];
    const float* k = (const float*)d_in[1];
    const float* v = (const float*)d_in[2];
    float* out = (float*)d_out;

    cudaFuncSetAttribute(qk_exp_kernel, cudaFuncAttributeMaxDynamicSharedMemorySize, SM1);
    cudaFuncSetAttribute(pv_kernel, cudaFuncAttributeMaxDynamicSharedMemorySize, SM2);

    zero_l_kernel<<<(BB * NN + 255) / 256, 256>>>();

    size_t nqk = (size_t)BB * NN * DD;
    cvt_kernel<<<(unsigned)((nqk + 255) / 256), 256>>>(q, k);

    qk_exp_kernel<<<dim3(NN / 128, NN / 128, BB), 256, SM1>>>();

    vt_kernel<<<dim3(NN / 32, DD / 32, BB), dim3(32, 8)>>>(v);

    pv_kernel<<<dim3(NN / 64, BB), 256, SM2>>>(out);
}

// round 6
// speedup vs baseline: 3.5957x; 1.1100x over previous
#include <cuda_runtime.h>
#include <math.h>
#include <stdint.h>

#define BB 4
#define NN 4096
#define DD 128

// ---------------- scratch (device globals; allocation-free) ----------------
__device__ float g_E[(size_t)BB * NN * NN];   // exp(S), tf32-rounded
__device__ float g_l[BB * NN];                // column sums over q
__device__ float g_Qt[(size_t)BB * NN * DD];  // RNA-tf32 rounded Q
__device__ float g_Kt[(size_t)BB * NN * DD];  // RNA-tf32 rounded K
__device__ float g_VT[(size_t)BB * DD * NN];  // V^T scaled by 1/l, tf32-rounded

// ---------------- helpers ----------------
__device__ __forceinline__ uint32_t smem_u32(const void* p) {
    uint32_t a;
    asm("{ .reg .u64 t; cvta.to.shared.u64 t, %1; cvt.u32.u64 %0, t; }" : "=r"(a) : "l"(p));
    return a;
}
__device__ __forceinline__ float to_tf32(float x) {
    uint32_t u;
    asm("cvt.rna.tf32.f32 %0, %1;" : "=r"(u) : "f"(x));
    return __uint_as_float(u);
}

#define CP_ASYNC16(s, g) asm volatile("cp.async.cg.shared.global [%0], [%1], 16;" :: "r"(s), "l"(g))
#define CP_COMMIT()      asm volatile("cp.async.commit_group;" ::: "memory")
#define CP_WAIT(n)       asm volatile("cp.async.wait_group %0;" :: "n"(n) : "memory")

// m16n8k8 tf32 MMA, fp32 accumulate (baseline PTX, sm_80+)
__device__ __forceinline__ void mma_tf32(float* c, const uint32_t* a, const uint32_t* b) {
    asm volatile(
        "mma.sync.aligned.m16n8k8.row.col.f32.tf32.tf32.f32 "
        "{%0,%1,%2,%3}, {%4,%5,%6,%7}, {%8,%9}, {%0,%1,%2,%3};"
        : "+f"(c[0]), "+f"(c[1]), "+f"(c[2]), "+f"(c[3])
        : "r"(a[0]), "r"(a[1]), "r"(a[2]), "r"(a[3]), "r"(b[0]), "r"(b[1]));
}

// SMEM tile: rows x 32 floats, row stride 36 floats (144B) -> conflict-free frags
// 256-thread loaders (qk): tiles 128x32
__device__ __forceinline__ void load_t128_256(uint32_t sdst, const float* g, size_t rstride, int tid) {
#pragma unroll
    for (int i = 0; i < 4; i++) {
        int idx = i * 256 + tid;
        int row = idx >> 3, c4 = idx & 7;
        CP_ASYNC16(sdst + row * 144 + c4 * 16, g + (size_t)row * rstride + c4 * 4);
    }
}
// 128-thread loaders (pv): tiles 64x32 and 128x32
__device__ __forceinline__ void load_t64_128(uint32_t sdst, const float* g, size_t rstride, int tid) {
#pragma unroll
    for (int i = 0; i < 4; i++) {
        int idx = i * 128 + tid;
        int row = idx >> 3, c4 = idx & 7;
        CP_ASYNC16(sdst + row * 144 + c4 * 16, g + (size_t)row * rstride + c4 * 4);
    }
}
__device__ __forceinline__ void load_t128_128(uint32_t sdst, const float* g, size_t rstride, int tid) {
#pragma unroll
    for (int i = 0; i < 8; i++) {
        int idx = i * 128 + tid;
        int row = idx >> 3, c4 = idx & 7;
        CP_ASYNC16(sdst + row * 144 + c4 * 16, g + (size_t)row * rstride + c4 * 4);
    }
}

// ---------------- small kernels ----------------
__global__ void cvt_kernel(const float* __restrict__ Q, const float* __restrict__ K) {
    size_t n = (size_t)BB * NN * DD;
    size_t i = (size_t)blockIdx.x * blockDim.x + threadIdx.x;
    if (i < n) {
        g_Qt[i] = to_tf32(Q[i]);
        g_Kt[i] = to_tf32(K[i]);
    }
    if (i < BB * NN) g_l[i] = 0.0f;
}
// VT[b][d][k] = rna(V[b][k][d] / l[b][k])
__global__ void vt_kernel(const float* __restrict__ V) {
    __shared__ float ts[32][33];
    int b = blockIdx.z, d0 = blockIdx.y * 32, k0 = blockIdx.x * 32;
    int tx = threadIdx.x, ty = threadIdx.y;
    const float* Vb = V + (size_t)b * NN * DD;
#pragma unroll
    for (int i = 0; i < 4; i++) {
        int r = ty + i * 8;
        ts[r][tx] = Vb[(size_t)(k0 + r) * DD + d0 + tx];
    }
    __syncthreads();
    float linv = 1.0f / g_l[b * NN + k0 + tx];
#pragma unroll
    for (int i = 0; i < 4; i++) {
        int d = ty + i * 8;
        g_VT[((size_t)b * DD + d0 + d) * NN + k0 + tx] = to_tf32(ts[tx][d] * linv);
    }
}

// ---------------- kernel 1: E = exp(QK^T/sqrt(D)), l = colsum(E) ----------------
// grid (32 kt, 32 qt, 4 b), 256 threads (8 warps, 2x4), tile 128x128, K=128 in 4 chunks.
// Single-sync pipeline: CP_WAIT -> syncthreads -> issue next -> compute.
#define TILEB (128 * 36 * 4)  // 18432
#define SM1 (4 * TILEB)       // 73728
__global__ __launch_bounds__(256, 2) void qk_exp_kernel() {
    const int b = blockIdx.z, qb = blockIdx.y * 128, kb = blockIdx.x * 128;
    const int tid = threadIdx.x, lane = tid & 31, wid = tid >> 5;
    const int wm = wid >> 2, wn = wid & 3;

    extern __shared__ __align__(16) char dyn[];
    uint32_t sbase = smem_u32(dyn);
    uint32_t sA[2] = { sbase, sbase + TILEB };
    uint32_t sB[2] = { sbase + 2 * TILEB, sbase + 3 * TILEB };
    const float* fA[2] = { (const float*)dyn, (const float*)(dyn + TILEB) };
    const float* fB[2] = { (const float*)(dyn + 2 * TILEB), (const float*)(dyn + 3 * TILEB) };

    const float* Qg = g_Qt + ((size_t)b * NN + qb) * DD;
    const float* Kg = g_Kt + ((size_t)b * NN + kb) * DD;

    float acc[4][4][4];
#pragma unroll
    for (int i = 0; i < 4; i++)
#pragma unroll
        for (int j = 0; j < 4; j++)
#pragma unroll
            for (int t = 0; t < 4; t++) acc[i][j][t] = 0.0f;

    load_t128_256(sA[0], Qg, DD, tid);
    load_t128_256(sB[0], Kg, DD, tid);
    CP_COMMIT();

#pragma unroll 1
    for (int c = 0; c < 4; c++) {
        CP_WAIT(0);       // my copies of tile c (issued in iter c-1) are done
        __syncthreads();  // everyone's tile-c data visible; buf (c+1)&1 free (all read in c-1)
        if (c + 1 < 4) {
            load_t128_256(sA[(c + 1) & 1], Qg + (c + 1) * 32, DD, tid);
            load_t128_256(sB[(c + 1) & 1], Kg + (c + 1) * 32, DD, tid);
            CP_COMMIT();  // overlaps compute of tile c
        }
        const float* A = fA[c & 1];
        const float* B = fB[c & 1];
#pragma unroll
        for (int ks = 0; ks < 4; ks++) {
            const int k0 = ks * 8;
            uint32_t af[4][4], bf[4][2];
#pragma unroll
            for (int i = 0; i < 4; i++) {
                int r0 = wm * 64 + i * 16 + (lane >> 2);
                af[i][0] = __float_as_uint(A[r0 * 36 + k0 + (lane & 3)]);
                af[i][1] = __float_as_uint(A[(r0 + 8) * 36 + k0 + (lane & 3)]);
                af[i][2] = __float_as_uint(A[r0 * 36 + k0 + 4 + (lane & 3)]);
                af[i][3] = __float_as_uint(A[(r0 + 8) * 36 + k0 + 4 + (lane & 3)]);
            }
#pragma unroll
            for (int j = 0; j < 4; j++) {
                int n0 = wn * 32 + j * 8 + (lane >> 2);
                bf[j][0] = __float_as_uint(B[n0 * 36 + k0 + (lane & 3)]);
                bf[j][1] = __float_as_uint(B[n0 * 36 + k0 + 4 + (lane & 3)]);
            }
#pragma unroll
            for (int i = 0; i < 4; i++)
#pragma unroll
                for (int j = 0; j < 4; j++) mma_tf32(acc[i][j], af[i], bf[j]);
        }
    }

    // epilogue: exp, tf32-round, store E, column sums
    const float SCALE = 0.08838834764831845f;
    float csum[4][2];
#pragma unroll
    for (int j = 0; j < 4; j++) { csum[j][0] = 0.0f; csum[j][1] = 0.0f; }

#pragma unroll
    for (int i = 0; i < 4; i++) {
        const int row0 = qb + wm * 64 + i * 16 + (lane >> 2);
#pragma unroll
        for (int j = 0; j < 4; j++) {
            float e0 = to_tf32(__expf(acc[i][j][0] * SCALE));
            float e1 = to_tf32(__expf(acc[i][j][1] * SCALE));
            float e2 = to_tf32(__expf(acc[i][j][2] * SCALE));
            float e3 = to_tf32(__expf(acc[i][j][3] * SCALE));
            const int col = kb + wn * 32 + j * 8 + (lane & 3) * 2;
            float2* p0 = (float2*)(g_E + ((size_t)b * NN + row0) * NN + col);
            float2* p1 = (float2*)(g_E + ((size_t)b * NN + row0 + 8) * NN + col);
            *p0 = make_float2(e0, e1);
            *p1 = make_float2(e2, e3);
            csum[j][0] += e0 + e2;
            csum[j][1] += e1 + e3;
        }
    }
#pragma unroll
    for (int j = 0; j < 4; j++) {
#pragma unroll
        for (int p = 0; p < 2; p++) {
            float v = csum[j][p];
            v += __shfl_xor_sync(0xffffffffu, v, 4);
            v += __shfl_xor_sync(0xffffffffu, v, 8);
            v += __shfl_xor_sync(0xffffffffu, v, 16);
            if (lane < 4)
                atomicAdd(&g_l[b * NN + kb + wn * 32 + j * 8 + lane * 2 + p], v);
        }
    }
}

// ---------------- kernel 2: O = E_norm @ V ----------------
// grid (64 qt, 4 b), 128 threads (4 warps), tile 64(q) x 128(d), warp 64x32,
// K=4096 in 128 chunks, 2-stage, single sync per iteration, occ 4.
#define TILEB64 (64 * 36 * 4)          // 9216
#define SM2 (2 * TILEB64 + 2 * TILEB)  // 55296
__global__ __launch_bounds__(128, 4) void pv_kernel(float* __restrict__ O) {
    const int b = blockIdx.y, qb = blockIdx.x * 64;
    const int tid = threadIdx.x, lane = tid & 31, wn = tid >> 5;

    extern __shared__ __align__(16) char dyn[];
    uint32_t sbase = smem_u32(dyn);
    uint32_t sA[2] = { sbase, sbase + TILEB64 };
    uint32_t sB[2] = { sbase + 2 * TILEB64, sbase + 2 * TILEB64 + TILEB };
    const float* fA[2] = { (const float*)dyn, (const float*)(dyn + TILEB64) };
    const float* fB[2] = { (const float*)(dyn + 2 * TILEB64),
                           (const float*)(dyn + 2 * TILEB64 + TILEB) };

    const float* Eg = g_E + ((size_t)b * NN + qb) * NN;
    const float* Vg = g_VT + (size_t)b * DD * NN;

    float acc[4][4][4];
#pragma unroll
    for (int i = 0; i < 4; i++)
#pragma unroll
        for (int j = 0; j < 4; j++)
#pragma unroll
            for (int t = 0; t < 4; t++) acc[i][j][t] = 0.0f;

    load_t64_128(sA[0], Eg, NN, tid);
    load_t128_128(sB[0], Vg, NN, tid);
    CP_COMMIT();

#pragma unroll 1
    for (int c = 0; c < 128; c++) {
        CP_WAIT(0);
        __syncthreads();
        if (c + 1 < 128) {
            load_t64_128(sA[(c + 1) & 1], Eg + (size_t)(c + 1) * 32, NN, tid);
            load_t128_128(sB[(c + 1) & 1], Vg + (size_t)(c + 1) * 32, NN, tid);
            CP_COMMIT();
        }
        const float* A = fA[c & 1];
        const float* B = fB[c & 1];
#pragma unroll
        for (int ks = 0; ks < 4; ks++) {
            const int k0 = ks * 8;
            uint32_t af[4][4], bf[4][2];
#pragma unroll
            for (int i = 0; i < 4; i++) {
                int r0 = i * 16 + (lane >> 2);
                af[i][0] = __float_as_uint(A[r0 * 36 + k0 + (lane & 3)]);
                af[i][1] = __float_as_uint(A[(r0 + 8) * 36 + k0 + (lane & 3)]);
                af[i][2] = __float_as_uint(A[r0 * 36 + k0 + 4 + (lane & 3)]);
                af[i][3] = __float_as_uint(A[(r0 + 8) * 36 + k0 + 4 + (lane & 3)]);
            }
#pragma unroll
            for (int j = 0; j < 4; j++) {
                int n0 = wn * 32 + j * 8 + (lane >> 2);
                bf[j][0] = __float_as_uint(B[n0 * 36 + k0 + (lane & 3)]);
                bf[j][1] = __float_as_uint(B[n0 * 36 + k0 + 4 + (lane & 3)]);
            }
#pragma unroll
            for (int i = 0; i < 4; i++)
#pragma unroll
                for (int j = 0; j < 4; j++) mma_tf32(acc[i][j], af[i], bf[j]);
        }
    }

#pragma unroll
    for (int i = 0; i < 4; i++) {
        const int row0 = qb + i * 16 + (lane >> 2);
#pragma unroll
        for (int j = 0; j < 4; j++) {
            const int col = wn * 32 + j * 8 + (lane & 3) * 2;
            float2* p0 = (float2*)(O + ((size_t)b * NN + row0) * DD + col);
            float2* p1 = (float2*)(O + ((size_t)b * NN + row0 + 8) * DD + col);
            *p0 = make_float2(acc[i][j][0], acc[i][j][1]);
            *p1 = make_float2(acc[i][j][2], acc[i][j][3]);
        }
    }
}

// ---------------- launch ----------------
extern "C" void kernel_launch(void* const* d_in, const int* in_sizes, int n_in,
                              void* d_out, int out_size) {
    const float* q = (const float*)d_in[0];
    const float* k = (const float*)d_in[1];
    const float* v = (const float*)d_in[2];
    float* out = (float*)d_out;

    cudaFuncSetAttribute(qk_exp_kernel, cudaFuncAttributeMaxDynamicSharedMemorySize, SM1);
    cudaFuncSetAttribute(pv_kernel, cudaFuncAttributeMaxDynamicSharedMemorySize, SM2);

    size_t nqk = (size_t)BB * NN * DD;
    cvt_kernel<<<(unsigned)((nqk + 255) / 256), 256>>>(q, k);

    qk_exp_kernel<<<dim3(NN / 128, NN / 128, BB), 256, SM1>>>();

    vt_kernel<<<dim3(NN / 32, DD / 32, BB), dim3(32, 8)>>>(v);

    pv_kernel<<<dim3(NN / 64, BB), 128, SM2>>>(out);
}

// round 7
// speedup vs baseline: 3.9415x; 1.0962x over previous
#include <cuda_runtime.h>
#include <math.h>
#include <stdint.h>

#define BB 4
#define NN 4096
#define DD 128
#define KSPLIT 8                 // pv split-K factor
#define CHUNKS_PER_SPLIT (128 / KSPLIT)  // 16 chunks of 32

// ---------------- scratch (device globals; allocation-free) ----------------
__device__ float g_E[(size_t)BB * NN * NN];   // exp(S), tf32-rounded
__device__ float g_l[BB * NN];                // column sums over q
__device__ float g_Qt[(size_t)BB * NN * DD];  // RNA-tf32 rounded Q
__device__ float g_Kt[(size_t)BB * NN * DD];  // RNA-tf32 rounded K
__device__ float g_VT[(size_t)BB * DD * NN];  // V^T scaled by 1/l, tf32-rounded
__device__ float g_Po[(size_t)KSPLIT * BB * NN * DD];  // pv split partials

// ---------------- helpers ----------------
__device__ __forceinline__ uint32_t smem_u32(const void* p) {
    uint32_t a;
    asm("{ .reg .u64 t; cvta.to.shared.u64 t, %1; cvt.u32.u64 %0, t; }" : "=r"(a) : "l"(p));
    return a;
}
__device__ __forceinline__ float to_tf32(float x) {
    uint32_t u;
    asm("cvt.rna.tf32.f32 %0, %1;" : "=r"(u) : "f"(x));
    return __uint_as_float(u);
}

#define CP_ASYNC16(s, g) asm volatile("cp.async.cg.shared.global [%0], [%1], 16;" :: "r"(s), "l"(g))
#define CP_COMMIT()      asm volatile("cp.async.commit_group;" ::: "memory")
#define CP_WAIT(n)       asm volatile("cp.async.wait_group %0;" :: "n"(n) : "memory")

// m16n8k8 tf32 MMA, fp32 accumulate (baseline PTX, sm_80+)
__device__ __forceinline__ void mma_tf32(float* c, const uint32_t* a, const uint32_t* b) {
    asm volatile(
        "mma.sync.aligned.m16n8k8.row.col.f32.tf32.tf32.f32 "
        "{%0,%1,%2,%3}, {%4,%5,%6,%7}, {%8,%9}, {%0,%1,%2,%3};"
        : "+f"(c[0]), "+f"(c[1]), "+f"(c[2]), "+f"(c[3])
        : "r"(a[0]), "r"(a[1]), "r"(a[2]), "r"(a[3]), "r"(b[0]), "r"(b[1]));
}

// SMEM tile: rows x 32 floats, row stride 36 floats (144B) -> conflict-free frags
__device__ __forceinline__ void load_t128_256(uint32_t sdst, const float* g, size_t rstride, int tid) {
#pragma unroll
    for (int i = 0; i < 4; i++) {
        int idx = i * 256 + tid;
        int row = idx >> 3, c4 = idx & 7;
        CP_ASYNC16(sdst + row * 144 + c4 * 16, g + (size_t)row * rstride + c4 * 4);
    }
}
__device__ __forceinline__ void load_t64_128(uint32_t sdst, const float* g, size_t rstride, int tid) {
#pragma unroll
    for (int i = 0; i < 4; i++) {
        int idx = i * 128 + tid;
        int row = idx >> 3, c4 = idx & 7;
        CP_ASYNC16(sdst + row * 144 + c4 * 16, g + (size_t)row * rstride + c4 * 4);
    }
}
__device__ __forceinline__ void load_t128_128(uint32_t sdst, const float* g, size_t rstride, int tid) {
#pragma unroll
    for (int i = 0; i < 8; i++) {
        int idx = i * 128 + tid;
        int row = idx >> 3, c4 = idx & 7;
        CP_ASYNC16(sdst + row * 144 + c4 * 16, g + (size_t)row * rstride + c4 * 4);
    }
}

// ---------------- small kernels ----------------
__global__ void cvt_kernel(const float* __restrict__ Q, const float* __restrict__ K) {
    size_t n = (size_t)BB * NN * DD;
    size_t i = (size_t)blockIdx.x * blockDim.x + threadIdx.x;
    if (i < n) {
        g_Qt[i] = to_tf32(Q[i]);
        g_Kt[i] = to_tf32(K[i]);
    }
    if (i < BB * NN) g_l[i] = 0.0f;
}
// VT[b][d][k] = rna(V[b][k][d] / l[b][k])
__global__ void vt_kernel(const float* __restrict__ V) {
    __shared__ float ts[32][33];
    int b = blockIdx.z, d0 = blockIdx.y * 32, k0 = blockIdx.x * 32;
    int tx = threadIdx.x, ty = threadIdx.y;
    const float* Vb = V + (size_t)b * NN * DD;
#pragma unroll
    for (int i = 0; i < 4; i++) {
        int r = ty + i * 8;
        ts[r][tx] = Vb[(size_t)(k0 + r) * DD + d0 + tx];
    }
    __syncthreads();
    float linv = 1.0f / g_l[b * NN + k0 + tx];
#pragma unroll
    for (int i = 0; i < 4; i++) {
        int d = ty + i * 8;
        g_VT[((size_t)b * DD + d0 + d) * NN + k0 + tx] = to_tf32(ts[tx][d] * linv);
    }
}
// O = sum of KSPLIT partials (deterministic order)
__global__ void reduce_kernel(float* __restrict__ O) {
    size_t i = ((size_t)blockIdx.x * blockDim.x + threadIdx.x) * 4;
    const size_t stride = (size_t)BB * NN * DD;
    if (i < stride) {
        float4 s = *(const float4*)(g_Po + i);
#pragma unroll
        for (int p = 1; p < KSPLIT; p++) {
            float4 t = *(const float4*)(g_Po + (size_t)p * stride + i);
            s.x += t.x; s.y += t.y; s.z += t.z; s.w += t.w;
        }
        *(float4*)(O + i) = s;
    }
}

// ---------------- kernel 1: E = exp(QK^T/sqrt(D)), l = colsum(E) ----------------
// grid (32 kt, 32 qt, 4 b), 256 threads (8 warps, 2x4), tile 128x128, K=128 in 4 chunks.
#define TILEB (128 * 36 * 4)  // 18432
#define SM1 (4 * TILEB)       // 73728
__global__ __launch_bounds__(256, 2) void qk_exp_kernel() {
    const int b = blockIdx.z, qb = blockIdx.y * 128, kb = blockIdx.x * 128;
    const int tid = threadIdx.x, lane = tid & 31, wid = tid >> 5;
    const int wm = wid >> 2, wn = wid & 3;

    extern __shared__ __align__(16) char dyn[];
    uint32_t sbase = smem_u32(dyn);
    uint32_t sA[2] = { sbase, sbase + TILEB };
    uint32_t sB[2] = { sbase + 2 * TILEB, sbase + 3 * TILEB };
    const float* fA[2] = { (const float*)dyn, (const float*)(dyn + TILEB) };
    const float* fB[2] = { (const float*)(dyn + 2 * TILEB), (const float*)(dyn + 3 * TILEB) };

    const float* Qg = g_Qt + ((size_t)b * NN + qb) * DD;
    const float* Kg = g_Kt + ((size_t)b * NN + kb) * DD;

    float acc[4][4][4];
#pragma unroll
    for (int i = 0; i < 4; i++)
#pragma unroll
        for (int j = 0; j < 4; j++)
#pragma unroll
            for (int t = 0; t < 4; t++) acc[i][j][t] = 0.0f;

    load_t128_256(sA[0], Qg, DD, tid);
    load_t128_256(sB[0], Kg, DD, tid);
    CP_COMMIT();

#pragma unroll 1
    for (int c = 0; c < 4; c++) {
        CP_WAIT(0);
        __syncthreads();
        if (c + 1 < 4) {
            load_t128_256(sA[(c + 1) & 1], Qg + (c + 1) * 32, DD, tid);
            load_t128_256(sB[(c + 1) & 1], Kg + (c + 1) * 32, DD, tid);
            CP_COMMIT();
        }
        const float* A = fA[c & 1];
        const float* B = fB[c & 1];
#pragma unroll
        for (int ks = 0; ks < 4; ks++) {
            const int k0 = ks * 8;
            uint32_t af[4][4], bf[4][2];
#pragma unroll
            for (int i = 0; i < 4; i++) {
                int r0 = wm * 64 + i * 16 + (lane >> 2);
                af[i][0] = __float_as_uint(A[r0 * 36 + k0 + (lane & 3)]);
                af[i][1] = __float_as_uint(A[(r0 + 8) * 36 + k0 + (lane & 3)]);
                af[i][2] = __float_as_uint(A[r0 * 36 + k0 + 4 + (lane & 3)]);
                af[i][3] = __float_as_uint(A[(r0 + 8) * 36 + k0 + 4 + (lane & 3)]);
            }
#pragma unroll
            for (int j = 0; j < 4; j++) {
                int n0 = wn * 32 + j * 8 + (lane >> 2);
                bf[j][0] = __float_as_uint(B[n0 * 36 + k0 + (lane & 3)]);
                bf[j][1] = __float_as_uint(B[n0 * 36 + k0 + 4 + (lane & 3)]);
            }
#pragma unroll
            for (int i = 0; i < 4; i++)
#pragma unroll
                for (int j = 0; j < 4; j++) mma_tf32(acc[i][j], af[i], bf[j]);
        }
    }

    const float SCALE = 0.08838834764831845f;
    float csum[4][2];
#pragma unroll
    for (int j = 0; j < 4; j++) { csum[j][0] = 0.0f; csum[j][1] = 0.0f; }

#pragma unroll
    for (int i = 0; i < 4; i++) {
        const int row0 = qb + wm * 64 + i * 16 + (lane >> 2);
#pragma unroll
        for (int j = 0; j < 4; j++) {
            float e0 = to_tf32(__expf(acc[i][j][0] * SCALE));
            float e1 = to_tf32(__expf(acc[i][j][1] * SCALE));
            float e2 = to_tf32(__expf(acc[i][j][2] * SCALE));
            float e3 = to_tf32(__expf(acc[i][j][3] * SCALE));
            const int col = kb + wn * 32 + j * 8 + (lane & 3) * 2;
            float2* p0 = (float2*)(g_E + ((size_t)b * NN + row0) * NN + col);
            float2* p1 = (float2*)(g_E + ((size_t)b * NN + row0 + 8) * NN + col);
            *p0 = make_float2(e0, e1);
            *p1 = make_float2(e2, e3);
            csum[j][0] += e0 + e2;
            csum[j][1] += e1 + e3;
        }
    }
#pragma unroll
    for (int j = 0; j < 4; j++) {
#pragma unroll
        for (int p = 0; p < 2; p++) {
            float v = csum[j][p];
            v += __shfl_xor_sync(0xffffffffu, v, 4);
            v += __shfl_xor_sync(0xffffffffu, v, 8);
            v += __shfl_xor_sync(0xffffffffu, v, 16);
            if (lane < 4)
                atomicAdd(&g_l[b * NN + kb + wn * 32 + j * 8 + lane * 2 + p], v);
        }
    }
}

// ---------------- kernel 2: partial O = E_norm @ V over one K-split ----------------
// grid (64 qt, KSPLIT, 4 b), 128 threads (4 warps), tile 64(q) x 128(d), warp 64x32,
// 16 chunks of 32, 2-stage, single sync per iteration, occ 4.
#define TILEB64 (64 * 36 * 4)          // 9216
#define SM2 (2 * TILEB64 + 2 * TILEB)  // 55296
__global__ __launch_bounds__(128, 4) void pv_kernel() {
    const int b = blockIdx.z, split = blockIdx.y, qb = blockIdx.x * 64;
    const int tid = threadIdx.x, lane = tid & 31, wn = tid >> 5;
    const int c0 = split * CHUNKS_PER_SPLIT;  // first 32-chunk of this split

    extern __shared__ __align__(16) char dyn[];
    uint32_t sbase = smem_u32(dyn);
    uint32_t sA[2] = { sbase, sbase + TILEB64 };
    uint32_t sB[2] = { sbase + 2 * TILEB64, sbase + 2 * TILEB64 + TILEB };
    const float* fA[2] = { (const float*)dyn, (const float*)(dyn + TILEB64) };
    const float* fB[2] = { (const float*)(dyn + 2 * TILEB64),
                           (const float*)(dyn + 2 * TILEB64 + TILEB) };

    const float* Eg = g_E + ((size_t)b * NN + qb) * NN;
    const float* Vg = g_VT + (size_t)b * DD * NN;

    float acc[4][4][4];
#pragma unroll
    for (int i = 0; i < 4; i++)
#pragma unroll
        for (int j = 0; j < 4; j++)
#pragma unroll
            for (int t = 0; t < 4; t++) acc[i][j][t] = 0.0f;

    load_t64_128(sA[0], Eg + (size_t)c0 * 32, NN, tid);
    load_t128_128(sB[0], Vg + (size_t)c0 * 32, NN, tid);
    CP_COMMIT();

#pragma unroll 1
    for (int c = 0; c < CHUNKS_PER_SPLIT; c++) {
        CP_WAIT(0);
        __syncthreads();
        if (c + 1 < CHUNKS_PER_SPLIT) {
            load_t64_128(sA[(c + 1) & 1], Eg + (size_t)(c0 + c + 1) * 32, NN, tid);
            load_t128_128(sB[(c + 1) & 1], Vg + (size_t)(c0 + c + 1) * 32, NN, tid);
            CP_COMMIT();
        }
        const float* A = fA[c & 1];
        const float* B = fB[c & 1];
#pragma unroll
        for (int ks = 0; ks < 4; ks++) {
            const int k0 = ks * 8;
            uint32_t af[4][4], bf[4][2];
#pragma unroll
            for (int i = 0; i < 4; i++) {
                int r0 = i * 16 + (lane >> 2);
                af[i][0] = __float_as_uint(A[r0 * 36 + k0 + (lane & 3)]);
                af[i][1] = __float_as_uint(A[(r0 + 8) * 36 + k0 + (lane & 3)]);
                af[i][2] = __float_as_uint(A[r0 * 36 + k0 + 4 + (lane & 3)]);
                af[i][3] = __float_as_uint(A[(r0 + 8) * 36 + k0 + 4 + (lane & 3)]);
            }
#pragma unroll
            for (int j = 0; j < 4; j++) {
                int n0 = wn * 32 + j * 8 + (lane >> 2);
                bf[j][0] = __float_as_uint(B[n0 * 36 + k0 + (lane & 3)]);
                bf[j][1] = __float_as_uint(B[n0 * 36 + k0 + 4 + (lane & 3)]);
            }
#pragma unroll
            for (int i = 0; i < 4; i++)
#pragma unroll
                for (int j = 0; j < 4; j++) mma_tf32(acc[i][j], af[i], bf[j]);
        }
    }

    float* Po = g_Po + (size_t)split * BB * NN * DD;
#pragma unroll
    for (int i = 0; i < 4; i++) {
        const int row0 = qb + i * 16 + (lane >> 2);
#pragma unroll
        for (int j = 0; j < 4; j++) {
            const int col = wn * 32 + j * 8 + (lane & 3) * 2;
            float2* p0 = (float2*)(Po + ((size_t)b * NN + row0) * DD + col);
            float2* p1 = (float2*)(Po + ((size_t)b * NN + row0 + 8) * DD + col);
            *p0 = make_float2(acc[i][j][0], acc[i][j][1]);
            *p1 = make_float2(acc[i][j][2], acc[i][j][3]);
        }
    }
}

// ---------------- launch ----------------
extern "C" void kernel_launch(void* const* d_in, const int* in_sizes, int n_in,
                              void* d_out, int out_size) {
    const float* q = (const float*)d_in[0];
    const float* k = (const float*)d_in[1];
    const float* v = (const float*)d_in[2];
    float* out = (float*)d_out;

    cudaFuncSetAttribute(qk_exp_kernel, cudaFuncAttributeMaxDynamicSharedMemorySize, SM1);
    cudaFuncSetAttribute(pv_kernel, cudaFuncAttributeMaxDynamicSharedMemorySize, SM2);

    size_t nqk = (size_t)BB * NN * DD;
    cvt_kernel<<<(unsigned)((nqk + 255) / 256), 256>>>(q, k);

    qk_exp_kernel<<<dim3(NN / 128, NN / 128, BB), 256, SM1>>>();

    vt_kernel<<<dim3(NN / 32, DD / 32, BB), dim3(32, 8)>>>(v);

    pv_kernel<<<dim3(NN / 64, KSPLIT, BB), 128, SM2>>>();

    size_t nout = (size_t)BB * NN * DD;
    reduce_kernel<<<(unsigned)((nout / 4 + 255) / 256), 256>>>(out);
}

// round 8
// speedup vs baseline: 4.6424x; 1.1778x over previous
#include <cuda_runtime.h>
#include <math.h>
#include <stdint.h>

#define BB 4
#define NN 4096
#define DD 128
#define KSPLIT 8                 // pv split-K factor
#define CHUNKS_PER_SPLIT (128 / KSPLIT)  // 16 chunks of 32

// ---------------- scratch (device globals; allocation-free) ----------------
__device__ float g_E[(size_t)BB * NN * NN];   // exp(S), tf32-rounded
__device__ float g_l[BB * NN];                // column sums over q
__device__ float g_Qt[(size_t)BB * NN * DD];  // RNA-tf32 rounded Q
__device__ float g_Kt[(size_t)BB * NN * DD];  // RNA-tf32 rounded K
__device__ float g_VT[(size_t)BB * DD * NN];  // V^T scaled by 1/l, tf32-rounded
__device__ float g_Po[(size_t)KSPLIT * BB * NN * DD];  // pv split partials

// ---------------- helpers ----------------
__device__ __forceinline__ uint32_t smem_u32(const void* p) {
    uint32_t a;
    asm("{ .reg .u64 t; cvta.to.shared.u64 t, %1; cvt.u32.u64 %0, t; }" : "=r"(a) : "l"(p));
    return a;
}
__device__ __forceinline__ float to_tf32(float x) {
    uint32_t u;
    asm("cvt.rna.tf32.f32 %0, %1;" : "=r"(u) : "f"(x));
    return __uint_as_float(u);
}

#define CP_ASYNC16(s, g) asm volatile("cp.async.cg.shared.global [%0], [%1], 16;" :: "r"(s), "l"(g))
#define CP_COMMIT()      asm volatile("cp.async.commit_group;" ::: "memory")
#define CP_WAIT(n)       asm volatile("cp.async.wait_group %0;" :: "n"(n) : "memory")

// m16n8k8 tf32 MMA, fp32 accumulate (baseline PTX, sm_80+)
__device__ __forceinline__ void mma_tf32(float* c, const uint32_t* a, const uint32_t* b) {
    asm volatile(
        "mma.sync.aligned.m16n8k8.row.col.f32.tf32.tf32.f32 "
        "{%0,%1,%2,%3}, {%4,%5,%6,%7}, {%8,%9}, {%0,%1,%2,%3};"
        : "+f"(c[0]), "+f"(c[1]), "+f"(c[2]), "+f"(c[3])
        : "r"(a[0]), "r"(a[1]), "r"(a[2]), "r"(a[3]), "r"(b[0]), "r"(b[1]));
}

// ldmatrix fragment loads (tf32-as-b16 trick: lane l -> row l>>2, f32 col l&3)
__device__ __forceinline__ void ldsm_x4(uint32_t* r, uint32_t addr) {
    asm volatile("ldmatrix.sync.aligned.m8n8.x4.shared.b16 {%0,%1,%2,%3}, [%4];"
                 : "=r"(r[0]), "=r"(r[1]), "=r"(r[2]), "=r"(r[3]) : "r"(addr));
}
__device__ __forceinline__ void ldsm_x2(uint32_t* r, uint32_t addr) {
    asm volatile("ldmatrix.sync.aligned.m8n8.x2.shared.b16 {%0,%1}, [%2];"
                 : "=r"(r[0]), "=r"(r[1]) : "r"(addr));
}

// SMEM tile: rows x 32 floats, row stride 36 floats (144B) -> conflict-free frags
__device__ __forceinline__ void load_t128_256(uint32_t sdst, const float* g, size_t rstride, int tid) {
#pragma unroll
    for (int i = 0; i < 4; i++) {
        int idx = i * 256 + tid;
        int row = idx >> 3, c4 = idx & 7;
        CP_ASYNC16(sdst + row * 144 + c4 * 16, g + (size_t)row * rstride + c4 * 4);
    }
}
__device__ __forceinline__ void load_t64_128(uint32_t sdst, const float* g, size_t rstride, int tid) {
#pragma unroll
    for (int i = 0; i < 4; i++) {
        int idx = i * 128 + tid;
        int row = idx >> 3, c4 = idx & 7;
        CP_ASYNC16(sdst + row * 144 + c4 * 16, g + (size_t)row * rstride + c4 * 4);
    }
}
__device__ __forceinline__ void load_t128_128(uint32_t sdst, const float* g, size_t rstride, int tid) {
#pragma unroll
    for (int i = 0; i < 8; i++) {
        int idx = i * 128 + tid;
        int row = idx >> 3, c4 = idx & 7;
        CP_ASYNC16(sdst + row * 144 + c4 * 16, g + (size_t)row * rstride + c4 * 4);
    }
}

// ---------------- small kernels ----------------
__global__ void cvt_kernel(const float* __restrict__ Q, const float* __restrict__ K) {
    size_t n = (size_t)BB * NN * DD;
    size_t i = (size_t)blockIdx.x * blockDim.x + threadIdx.x;
    if (i < n) {
        g_Qt[i] = to_tf32(Q[i]);
        g_Kt[i] = to_tf32(K[i]);
    }
    if (i < BB * NN) g_l[i] = 0.0f;
}
// VT[b][d][k] = rna(V[b][k][d] / l[b][k])
__global__ void vt_kernel(const float* __restrict__ V) {
    __shared__ float ts[32][33];
    int b = blockIdx.z, d0 = blockIdx.y * 32, k0 = blockIdx.x * 32;
    int tx = threadIdx.x, ty = threadIdx.y;
    const float* Vb = V + (size_t)b * NN * DD;
#pragma unroll
    for (int i = 0; i < 4; i++) {
        int r = ty + i * 8;
        ts[r][tx] = Vb[(size_t)(k0 + r) * DD + d0 + tx];
    }
    __syncthreads();
    float linv = 1.0f / g_l[b * NN + k0 + tx];
#pragma unroll
    for (int i = 0; i < 4; i++) {
        int d = ty + i * 8;
        g_VT[((size_t)b * DD + d0 + d) * NN + k0 + tx] = to_tf32(ts[tx][d] * linv);
    }
}
// O = sum of KSPLIT partials (deterministic order)
__global__ void reduce_kernel(float* __restrict__ O) {
    size_t i = ((size_t)blockIdx.x * blockDim.x + threadIdx.x) * 4;
    const size_t stride = (size_t)BB * NN * DD;
    if (i < stride) {
        float4 s = *(const float4*)(g_Po + i);
#pragma unroll
        for (int p = 1; p < KSPLIT; p++) {
            float4 t = *(const float4*)(g_Po + (size_t)p * stride + i);
            s.x += t.x; s.y += t.y; s.z += t.z; s.w += t.w;
        }
        *(float4*)(O + i) = s;
    }
}

// ---------------- kernel 1: E = exp(QK^T/sqrt(D)), l = colsum(E) ----------------
// grid (32 kt, 32 qt, 4 b), 256 threads (8 warps, 2x4), tile 128x128, K=128 in 4 chunks.
#define TILEB (128 * 36 * 4)  // 18432
#define SM1 (4 * TILEB)       // 73728
__global__ __launch_bounds__(256, 2) void qk_exp_kernel() {
    const int b = blockIdx.z, qb = blockIdx.y * 128, kb = blockIdx.x * 128;
    const int tid = threadIdx.x, lane = tid & 31, wid = tid >> 5;
    const int wm = wid >> 2, wn = wid & 3;

    extern __shared__ __align__(16) char dyn[];
    uint32_t sbase = smem_u32(dyn);
    uint32_t sA[2] = { sbase, sbase + TILEB };
    uint32_t sB[2] = { sbase + 2 * TILEB, sbase + 3 * TILEB };

    const float* Qg = g_Qt + ((size_t)b * NN + qb) * DD;
    const float* Kg = g_Kt + ((size_t)b * NN + kb) * DD;

    // ldmatrix per-lane row/col offsets (bytes) within a tile
    const int lr = lane & 7, lg = (lane >> 3) & 1, lh = lane >> 4;
    uint32_t a_off[4], b_off[4];
#pragma unroll
    for (int i = 0; i < 4; i++)
        a_off[i] = (uint32_t)(wm * 64 + i * 16 + lr + lg * 8) * 144 + (uint32_t)lh * 16;
#pragma unroll
    for (int j = 0; j < 4; j++)
        b_off[j] = (uint32_t)(wn * 32 + j * 8 + lr) * 144 + (uint32_t)lg * 16;

    float acc[4][4][4];
#pragma unroll
    for (int i = 0; i < 4; i++)
#pragma unroll
        for (int j = 0; j < 4; j++)
#pragma unroll
            for (int t = 0; t < 4; t++) acc[i][j][t] = 0.0f;

    load_t128_256(sA[0], Qg, DD, tid);
    load_t128_256(sB[0], Kg, DD, tid);
    CP_COMMIT();

#pragma unroll 1
    for (int c = 0; c < 4; c++) {
        CP_WAIT(0);
        __syncthreads();
        if (c + 1 < 4) {
            load_t128_256(sA[(c + 1) & 1], Qg + (c + 1) * 32, DD, tid);
            load_t128_256(sB[(c + 1) & 1], Kg + (c + 1) * 32, DD, tid);
            CP_COMMIT();
        }
        const uint32_t Ab = sA[c & 1], Bb = sB[c & 1];
#pragma unroll
        for (int ks = 0; ks < 4; ks++) {
            const uint32_t k0b = ks * 32;  // 8 f32 per step * 4B
            uint32_t af[4][4], bf[4][2];
#pragma unroll
            for (int i = 0; i < 4; i++) ldsm_x4(af[i], Ab + a_off[i] + k0b);
#pragma unroll
            for (int j = 0; j < 4; j++) ldsm_x2(bf[j], Bb + b_off[j] + k0b);
#pragma unroll
            for (int i = 0; i < 4; i++)
#pragma unroll
                for (int j = 0; j < 4; j++) mma_tf32(acc[i][j], af[i], bf[j]);
        }
    }

    const float SCALE = 0.08838834764831845f;
    float csum[4][2];
#pragma unroll
    for (int j = 0; j < 4; j++) { csum[j][0] = 0.0f; csum[j][1] = 0.0f; }

#pragma unroll
    for (int i = 0; i < 4; i++) {
        const int row0 = qb + wm * 64 + i * 16 + (lane >> 2);
#pragma unroll
        for (int j = 0; j < 4; j++) {
            float e0 = to_tf32(__expf(acc[i][j][0] * SCALE));
            float e1 = to_tf32(__expf(acc[i][j][1] * SCALE));
            float e2 = to_tf32(__expf(acc[i][j][2] * SCALE));
            float e3 = to_tf32(__expf(acc[i][j][3] * SCALE));
            const int col = kb + wn * 32 + j * 8 + (lane & 3) * 2;
            float2* p0 = (float2*)(g_E + ((size_t)b * NN + row0) * NN + col);
            float2* p1 = (float2*)(g_E + ((size_t)b * NN + row0 + 8) * NN + col);
            *p0 = make_float2(e0, e1);
            *p1 = make_float2(e2, e3);
            csum[j][0] += e0 + e2;
            csum[j][1] += e1 + e3;
        }
    }
#pragma unroll
    for (int j = 0; j < 4; j++) {
#pragma unroll
        for (int p = 0; p < 2; p++) {
            float v = csum[j][p];
            v += __shfl_xor_sync(0xffffffffu, v, 4);
            v += __shfl_xor_sync(0xffffffffu, v, 8);
            v += __shfl_xor_sync(0xffffffffu, v, 16);
            if (lane < 4)
                atomicAdd(&g_l[b * NN + kb + wn * 32 + j * 8 + lane * 2 + p], v);
        }
    }
}

// ---------------- kernel 2: partial O = E_norm @ V over one K-split ----------------
// grid (64 qt, KSPLIT, 4 b), 128 threads (4 warps), tile 64(q) x 128(d), warp 64x32,
// 16 chunks of 32, 2-stage, single sync per iteration, occ 4.
#define TILEB64 (64 * 36 * 4)          // 9216
#define SM2 (2 * TILEB64 + 2 * TILEB)  // 55296
__global__ __launch_bounds__(128, 4) void pv_kernel() {
    const int b = blockIdx.z, split = blockIdx.y, qb = blockIdx.x * 64;
    const int tid = threadIdx.x, lane = tid & 31, wn = tid >> 5;
    const int c0 = split * CHUNKS_PER_SPLIT;

    extern __shared__ __align__(16) char dyn[];
    uint32_t sbase = smem_u32(dyn);
    uint32_t sA[2] = { sbase, sbase + TILEB64 };
    uint32_t sB[2] = { sbase + 2 * TILEB64, sbase + 2 * TILEB64 + TILEB };

    const float* Eg = g_E + ((size_t)b * NN + qb) * NN;
    const float* Vg = g_VT + (size_t)b * DD * NN;

    const int lr = lane & 7, lg = (lane >> 3) & 1, lh = lane >> 4;
    uint32_t a_off[4], b_off[4];
#pragma unroll
    for (int i = 0; i < 4; i++)
        a_off[i] = (uint32_t)(i * 16 + lr + lg * 8) * 144 + (uint32_t)lh * 16;
#pragma unroll
    for (int j = 0; j < 4; j++)
        b_off[j] = (uint32_t)(wn * 32 + j * 8 + lr) * 144 + (uint32_t)lg * 16;

    float acc[4][4][4];
#pragma unroll
    for (int i = 0; i < 4; i++)
#pragma unroll
        for (int j = 0; j < 4; j++)
#pragma unroll
            for (int t = 0; t < 4; t++) acc[i][j][t] = 0.0f;

    load_t64_128(sA[0], Eg + (size_t)c0 * 32, NN, tid);
    load_t128_128(sB[0], Vg + (size_t)c0 * 32, NN, tid);
    CP_COMMIT();

#pragma unroll 1
    for (int c = 0; c < CHUNKS_PER_SPLIT; c++) {
        CP_WAIT(0);
        __syncthreads();
        if (c + 1 < CHUNKS_PER_SPLIT) {
            load_t64_128(sA[(c + 1) & 1], Eg + (size_t)(c0 + c + 1) * 32, NN, tid);
            load_t128_128(sB[(c + 1) & 1], Vg + (size_t)(c0 + c + 1) * 32, NN, tid);
            CP_COMMIT();
        }
        const uint32_t Ab = sA[c & 1], Bb = sB[c & 1];
#pragma unroll
        for (int ks = 0; ks < 4; ks++) {
            const uint32_t k0b = ks * 32;
            uint32_t af[4][4], bf[4][2];
#pragma unroll
            for (int i = 0; i < 4; i++) ldsm_x4(af[i], Ab + a_off[i] + k0b);
#pragma unroll
            for (int j = 0; j < 4; j++) ldsm_x2(bf[j], Bb + b_off[j] + k0b);
#pragma unroll
            for (int i = 0; i < 4; i++)
#pragma unroll
                for (int j = 0; j < 4; j++) mma_tf32(acc[i][j], af[i], bf[j]);
        }
    }

    float* Po = g_Po + (size_t)split * BB * NN * DD;
#pragma unroll
    for (int i = 0; i < 4; i++) {
        const int row0 = qb + i * 16 + (lane >> 2);
#pragma unroll
        for (int j = 0; j < 4; j++) {
            const int col = wn * 32 + j * 8 + (lane & 3) * 2;
            float2* p0 = (float2*)(Po + ((size_t)b * NN + row0) * DD + col);
            float2* p1 = (float2*)(Po + ((size_t)b * NN + row0 + 8) * DD + col);
            *p0 = make_float2(acc[i][j][0], acc[i][j][1]);
            *p1 = make_float2(acc[i][j][2], acc[i][j][3]);
        }
    }
}

// ---------------- launch ----------------
extern "C" void kernel_launch(void* const* d_in, const int* in_sizes, int n_in,
                              void* d_out, int out_size) {
    const float* q = (const float*)d_in[0];
    const float* k = (const float*)d_in[1];
    const float* v = (const float*)d_in[2];
    float* out = (float*)d_out;

    cudaFuncSetAttribute(qk_exp_kernel, cudaFuncAttributeMaxDynamicSharedMemorySize, SM1);
    cudaFuncSetAttribute(pv_kernel, cudaFuncAttributeMaxDynamicSharedMemorySize, SM2);

    size_t nqk = (size_t)BB * NN * DD;
    cvt_kernel<<<(unsigned)((nqk + 255) / 256), 256>>>(q, k);

    qk_exp_kernel<<<dim3(NN / 128, NN / 128, BB), 256, SM1>>>();

    vt_kernel<<<dim3(NN / 32, DD / 32, BB), dim3(32, 8)>>>(v);

    pv_kernel<<<dim3(NN / 64, KSPLIT, BB), 128, SM2>>>();

    size_t nout = (size_t)BB * NN * DD;
    reduce_kernel<<<(unsigned)((nout / 4 + 255) / 256), 256>>>(out);
}